// round 15
// baseline (speedup 1.0000x reference)
#include <cuda_runtime.h>
#include <math_constants.h>
#include <cstdint>

#define B_  4
#define C_  512
#define HC_ 256
#define N_  4096

// ---------------------------------------------------------------------------
// K-group permutation: within each 8-wide K group, position p holds
// k = (0,4,1,5,2,6,3,7)[p] so that fragment pairs (k, k+4) are adjacent.
// ---------------------------------------------------------------------------
__host__ __device__ __forceinline__ int perm8(int q)  { return ((q & 3) << 1) | (q >> 2); }
__device__ __forceinline__ int permpos(int c) { return (c & ~7) | perm8(c & 7); }

// ---------------------------------------------------------------------------
// Device scratch (all K-contraction dims stored permuted)
// ---------------------------------------------------------------------------
__device__ float g_xt[(size_t)B_ * N_ * C_];    // x^T: [b][n][c-perm]
__device__ float g_Wp[(size_t)(HC_ + HC_ + C_) * C_]; // Wf|Wg|Wh, [o][c-perm]
__device__ float g_ft[(size_t)B_ * N_ * HC_];   // f^T: [b][n][hc-perm]  (fp32)
__device__ float g_gt[(size_t)B_ * N_ * HC_];   // g^T: [b][n][hc-perm]  (tf32-rounded)
__device__ float g_h [(size_t)B_ * C_ * N_];    // h:   [b][c][n-perm]   (tf32-rounded)
__device__ float g_E [(size_t)B_ * N_ * N_];    // energy/corr [b][j][k-perm]
__device__ float g_part[(size_t)B_ * 512 * N_]; // colmean partials (8 rows each)

// ---------------------------------------------------------------------------
// Helpers (baseline PTX only — ptxas targets sm_103, no 'a'-gated instrs)
// ---------------------------------------------------------------------------
__device__ __forceinline__ uint32_t su32(const void* p) {
    uint32_t a;
    asm("{ .reg .u64 t; cvta.to.shared.u64 t, %1; cvt.u32.u64 %0, t; }" : "=r"(a) : "l"(p));
    return a;
}
__device__ __forceinline__ void cp_async16(uint32_t dst, const void* src) {
    asm volatile("cp.async.cg.shared.global [%0], [%1], 16;" :: "r"(dst), "l"(src) : "memory");
}
__device__ __forceinline__ void cp_commit() {
    asm volatile("cp.async.commit_group;" ::: "memory");
}
__device__ __forceinline__ void cp_wait0() {
    asm volatile("cp.async.wait_group 0;" ::: "memory");
}
__device__ __forceinline__ void cp_wait1() {
    asm volatile("cp.async.wait_group 1;" ::: "memory");
}
__device__ __forceinline__ uint32_t f2tf(float f) {
    uint32_t r;
    asm("cvt.rna.tf32.f32 %0, %1;" : "=r"(r) : "f"(f));
    return r;
}
// Truncation-based split: hi = top tf32 bits (LOP3), lo = v - hi (exact).
__device__ __forceinline__ void split_m(float v, uint32_t& hi, uint32_t& lo) {
    hi = __float_as_uint(v) & 0xFFFFE000u;
    lo = __float_as_uint(v - __uint_as_float(hi));
}
__device__ __forceinline__ void mma_tf32(float* d, const uint32_t* a, const uint32_t* b) {
    asm volatile(
        "mma.sync.aligned.m16n8k8.row.col.f32.tf32.tf32.f32 "
        "{%0,%1,%2,%3}, {%4,%5,%6,%7}, {%8,%9}, {%0,%1,%2,%3};"
        : "+f"(d[0]), "+f"(d[1]), "+f"(d[2]), "+f"(d[3])
        : "r"(a[0]), "r"(a[1]), "r"(a[2]), "r"(a[3]), "r"(b[0]), "r"(b[1]));
}

// fast exp(t) for t <= 0: exp2 via degree-5 minimax poly on FMA pipe (no MUFU)
__device__ __forceinline__ float fast_exp_neg(float t) {
    float z = fmaxf(t * 1.4426950408889634f, -120.0f);
    float fi = floorf(z);
    float f = z - fi;
    float p =              0.00133335581f;
    p = fmaf(p, f,         0.00961812910f);
    p = fmaf(p, f,         0.0555041086f);
    p = fmaf(p, f,         0.240226462f);
    p = fmaf(p, f,         0.693147182f);
    p = fmaf(p, f,         1.0f);
    return p * __int_as_float(((int)fi + 127) << 23);
}

// smem float-index with XOR swizzle: row stride 32 floats (128B), 16B chunks
#define SWZ(r, k) (((r) * 32) + ((k) ^ (((r) & 7) * 4)))

extern __shared__ float dynsm_f[];

// ---------------------------------------------------------------------------
// Narrow GEMM core (128x128 tile, 3-stage, 2 CTAs/SM): proj + energy.
// ---------------------------------------------------------------------------
template <int PASSES>
__device__ __forceinline__ void gemm_core(
    const float* __restrict__ A, int lda,
    const float* __restrict__ Bm, int ldb,
    int nK, float acc[4][4][4])
{
    float* sm = dynsm_f;
    const int tid  = threadIdx.x;
    const int lr   = tid >> 3;
    const int lc4  = (tid & 7) * 4;
    const int lane = tid & 31, warp = tid >> 5;
    const int wr = warp >> 2, wc = warp & 3;
    const int g = lane >> 2, tg = lane & 3;
    const int fchunk = tg >> 1;
    const int foff   = (tg & 1) << 1;

    auto issue = [&](int s, int kt) {
        const int k0 = kt * 32;
        float* sa = sm + s * 8192;
        float* sb = sa + 4096;
        #pragma unroll
        for (int p = 0; p < 4; ++p) {
            const int r = p * 32 + lr;
            cp_async16(su32(&sa[SWZ(r, lc4)]), &A [(size_t)r * lda + k0 + lc4]);
            cp_async16(su32(&sb[SWZ(r, lc4)]), &Bm[(size_t)r * ldb + k0 + lc4]);
        }
        cp_commit();
    };

    issue(0, 0);
    if (nK > 1) issue(1, 1);

    for (int kt = 0; kt < nK; ++kt) {
        const int s = kt % 3;
        if (kt + 1 < nK) cp_wait1(); else cp_wait0();
        __syncthreads();
        if (kt + 2 < nK) issue((kt + 2) % 3, kt + 2);

        const float* sa = sm + s * 8192;
        const float* sb = sa + 4096;
        #pragma unroll
        for (int k8 = 0; k8 < 4; ++k8) {
            const int chunk = (k8 << 1) | fchunk;
            uint32_t afh[4][4], afl[4][4], bfh[4][2], bfl[4][2];
            #pragma unroll
            for (int am = 0; am < 4; ++am) {
                const int r0 = wr * 64 + am * 16 + g;
                const int r1 = r0 + 8;
                float2 p0 = *reinterpret_cast<const float2*>(
                    &sa[r0 * 32 + ((chunk ^ (r0 & 7)) << 2) + foff]);
                float2 p1 = *reinterpret_cast<const float2*>(
                    &sa[r1 * 32 + ((chunk ^ (r1 & 7)) << 2) + foff]);
                if (PASSES >= 2) {
                    split_m(p0.x, afh[am][0], afl[am][0]);
                    split_m(p1.x, afh[am][1], afl[am][1]);
                    split_m(p0.y, afh[am][2], afl[am][2]);
                    split_m(p1.y, afh[am][3], afl[am][3]);
                } else {
                    afh[am][0] = __float_as_uint(p0.x);
                    afh[am][1] = __float_as_uint(p1.x);
                    afh[am][2] = __float_as_uint(p0.y);
                    afh[am][3] = __float_as_uint(p1.y);
                }
            }
            #pragma unroll
            for (int bn = 0; bn < 4; ++bn) {
                const int rb = wc * 32 + bn * 8 + g;
                float2 q = *reinterpret_cast<const float2*>(
                    &sb[rb * 32 + ((chunk ^ (rb & 7)) << 2) + foff]);
                if (PASSES == 3) {
                    split_m(q.x, bfh[bn][0], bfl[bn][0]);
                    split_m(q.y, bfh[bn][1], bfl[bn][1]);
                } else {
                    bfh[bn][0] = __float_as_uint(q.x);
                    bfh[bn][1] = __float_as_uint(q.y);
                }
            }
            #pragma unroll
            for (int am = 0; am < 4; ++am)
                #pragma unroll
                for (int bn = 0; bn < 4; ++bn)
                    mma_tf32(acc[am][bn], afh[am], bfh[bn]);
            if (PASSES == 3) {
                #pragma unroll
                for (int am = 0; am < 4; ++am)
                    #pragma unroll
                    for (int bn = 0; bn < 4; ++bn)
                        mma_tf32(acc[am][bn], afh[am], bfl[bn]);
            }
            if (PASSES >= 2) {
                #pragma unroll
                for (int am = 0; am < 4; ++am)
                    #pragma unroll
                    for (int bn = 0; bn < 4; ++bn)
                        mma_tf32(acc[am][bn], afl[am], bfh[bn]);
            }
        }
    }
}

// ---------------------------------------------------------------------------
// WIDE GEMM core: D[128 x 256], 2-stage, 1 CTA/SM. Residual only.
// ---------------------------------------------------------------------------
template <int PASSES>
__device__ __forceinline__ void gemm_core_w(
    const float* __restrict__ A, int lda,
    const float* __restrict__ Bm, int ldb,
    int nK, float acc[4][8][4])
{
    float* sm = dynsm_f;
    const int tid  = threadIdx.x;
    const int lr   = tid >> 3;
    const int lc4  = (tid & 7) * 4;
    const int lane = tid & 31, warp = tid >> 5;
    const int wr = warp >> 2, wc = warp & 3;
    const int g = lane >> 2, tg = lane & 3;
    const int fchunk = tg >> 1;
    const int foff   = (tg & 1) << 1;

    auto issue = [&](int s, int kt) {
        const int k0 = kt * 32;
        float* sa = sm + s * 12288;
        float* sb = sa + 4096;
        #pragma unroll
        for (int p = 0; p < 4; ++p) {
            const int r = p * 32 + lr;
            cp_async16(su32(&sa[SWZ(r, lc4)]), &A[(size_t)r * lda + k0 + lc4]);
        }
        #pragma unroll
        for (int p = 0; p < 8; ++p) {
            const int r = p * 32 + lr;
            cp_async16(su32(&sb[SWZ(r, lc4)]), &Bm[(size_t)r * ldb + k0 + lc4]);
        }
        cp_commit();
    };

    issue(0, 0);

    for (int kt = 0; kt < nK; ++kt) {
        const int s = kt & 1;
        cp_wait0();
        __syncthreads();
        if (kt + 1 < nK) issue(s ^ 1, kt + 1);

        const float* sa = sm + s * 12288;
        const float* sb = sa + 4096;
        #pragma unroll
        for (int k8 = 0; k8 < 4; ++k8) {
            const int chunk = (k8 << 1) | fchunk;
            uint32_t afh[4][4], afl[4][4], bfh[8][2], bfl[8][2];
            #pragma unroll
            for (int am = 0; am < 4; ++am) {
                const int r0 = wr * 64 + am * 16 + g;
                const int r1 = r0 + 8;
                float2 p0 = *reinterpret_cast<const float2*>(
                    &sa[r0 * 32 + ((chunk ^ (r0 & 7)) << 2) + foff]);
                float2 p1 = *reinterpret_cast<const float2*>(
                    &sa[r1 * 32 + ((chunk ^ (r1 & 7)) << 2) + foff]);
                if (PASSES >= 2) {
                    split_m(p0.x, afh[am][0], afl[am][0]);
                    split_m(p1.x, afh[am][1], afl[am][1]);
                    split_m(p0.y, afh[am][2], afl[am][2]);
                    split_m(p1.y, afh[am][3], afl[am][3]);
                } else {
                    afh[am][0] = __float_as_uint(p0.x);
                    afh[am][1] = __float_as_uint(p1.x);
                    afh[am][2] = __float_as_uint(p0.y);
                    afh[am][3] = __float_as_uint(p1.y);
                }
            }
            #pragma unroll
            for (int bn = 0; bn < 8; ++bn) {
                const int rb = wc * 64 + bn * 8 + g;
                float2 q = *reinterpret_cast<const float2*>(
                    &sb[rb * 32 + ((chunk ^ (rb & 7)) << 2) + foff]);
                if (PASSES == 3) {
                    split_m(q.x, bfh[bn][0], bfl[bn][0]);
                    split_m(q.y, bfh[bn][1], bfl[bn][1]);
                } else {
                    bfh[bn][0] = __float_as_uint(q.x);
                    bfh[bn][1] = __float_as_uint(q.y);
                }
            }
            #pragma unroll
            for (int am = 0; am < 4; ++am)
                #pragma unroll
                for (int bn = 0; bn < 8; ++bn)
                    mma_tf32(acc[am][bn], afh[am], bfh[bn]);
            if (PASSES == 3) {
                #pragma unroll
                for (int am = 0; am < 4; ++am)
                    #pragma unroll
                    for (int bn = 0; bn < 8; ++bn)
                        mma_tf32(acc[am][bn], afh[am], bfl[bn]);
            }
            if (PASSES >= 2) {
                #pragma unroll
                for (int am = 0; am < 4; ++am)
                    #pragma unroll
                    for (int bn = 0; bn < 8; ++bn)
                        mma_tf32(acc[am][bn], afl[am], bfh[bn]);
            }
        }
    }
}

// ---------------------------------------------------------------------------
// Epilogues
// ---------------------------------------------------------------------------
__device__ __forceinline__ void epi_store_perm(
    float acc[4][4][4], float* __restrict__ Out, int ld,
    const float* __restrict__ bias_col, const float* __restrict__ bias_row,
    bool round_tf)
{
    const int lane = threadIdx.x & 31, warp = threadIdx.x >> 5;
    const int wr = warp >> 2, wc = warp & 3;
    const int g = lane >> 2, tg = lane & 3;
    #pragma unroll
    for (int am = 0; am < 4; ++am) {
        const int r = wr * 64 + am * 16 + g;
        const float br0 = bias_row ? bias_row[r]     : 0.f;
        const float br1 = bias_row ? bias_row[r + 8] : 0.f;
        #pragma unroll
        for (int bn = 0; bn < 4; ++bn) {
            const int c = wc * 32 + bn * 8 + tg * 2;
            const float b0 = bias_col ? bias_col[c]     : 0.f;
            const float b1 = bias_col ? bias_col[c + 1] : 0.f;
            float e0 = acc[am][bn][0] + b0 + br0;
            float e1 = acc[am][bn][1] + b1 + br0;
            float e2 = acc[am][bn][2] + b0 + br1;
            float e3 = acc[am][bn][3] + b1 + br1;
            if (round_tf) {
                e0 = __uint_as_float(f2tf(e0));
                e1 = __uint_as_float(f2tf(e1));
                e2 = __uint_as_float(f2tf(e2));
                e3 = __uint_as_float(f2tf(e3));
            }
            const int p0 = (c & ~7) | perm8(c & 7);
            const int p1 = (c & ~7) | perm8((c & 7) + 1);
            Out[(size_t)r       * ld + p0] = e0;
            Out[(size_t)r       * ld + p1] = e1;
            Out[(size_t)(r + 8) * ld + p0] = e2;
            Out[(size_t)(r + 8) * ld + p1] = e3;
        }
    }
}

// Wide epilogue, natural columns (residual -> harness out).
__device__ __forceinline__ void epi_store_w(
    float acc[4][8][4], float* __restrict__ Out, int ld)
{
    const int lane = threadIdx.x & 31, warp = threadIdx.x >> 5;
    const int wr = warp >> 2, wc = warp & 3;
    const int g = lane >> 2, tg = lane & 3;
    #pragma unroll
    for (int am = 0; am < 4; ++am) {
        const int r = wr * 64 + am * 16 + g;
        #pragma unroll
        for (int bn = 0; bn < 8; ++bn) {
            const int c = wc * 64 + bn * 8 + tg * 2;
            float2 v0 = { acc[am][bn][0], acc[am][bn][1] };
            float2 v1 = { acc[am][bn][2], acc[am][bn][3] };
            *reinterpret_cast<float2*>(&Out[(size_t)r       * ld + c]) = v0;
            *reinterpret_cast<float2*>(&Out[(size_t)(r + 8) * ld + c]) = v1;
        }
    }
}

// ---------------------------------------------------------------------------
// Producers
// ---------------------------------------------------------------------------
__global__ __launch_bounds__(256) void permute_w_kernel(
    const float* __restrict__ Wf, const float* __restrict__ Wg,
    const float* __restrict__ Wh)
{
    const int i = blockIdx.x * 256 + threadIdx.x;
    const int NW = (HC_ + HC_ + C_) * C_;
    if (i >= NW) return;
    float v;
    if (i < HC_ * C_)           v = Wf[i];
    else if (i < 2 * HC_ * C_)  v = Wg[i - HC_ * C_];
    else                        v = Wh[i - 2 * HC_ * C_];
    const int o = i / C_, c = i % C_;
    g_Wp[(size_t)o * C_ + permpos(c)] = v;
}

__global__ __launch_bounds__(256) void transpose_x_kernel(const float* __restrict__ x)
{
    __shared__ float t[32][33];
    const int b = blockIdx.z, n0 = blockIdx.x * 32, c0 = blockIdx.y * 32;
    const int tx = threadIdx.x, ty = threadIdx.y;
    const float* X = x + (size_t)b * C_ * N_;
    float* XT = g_xt + (size_t)b * N_ * C_;
    #pragma unroll
    for (int i = 0; i < 4; ++i)
        t[ty + i * 8][tx] = X[(size_t)(c0 + ty + i * 8) * N_ + n0 + tx];
    __syncthreads();
    const int cp = c0 + permpos(tx);
    #pragma unroll
    for (int i = 0; i < 4; ++i)
        XT[(size_t)(n0 + ty + i * 8) * C_ + cp] = t[tx][ty + i * 8];
}

// ---------------------------------------------------------------------------
// Merged projection kernel (narrow core, 3xTF32).
// ---------------------------------------------------------------------------
__global__ __launch_bounds__(256, 2) void proj_kernel(
    const float* __restrict__ bf, const float* __restrict__ bg,
    const float* __restrict__ bh)
{
    const int b = blockIdx.z, n0 = blockIdx.x * 128, yt = blockIdx.y;
    float acc[4][4][4] = {};

    if (yt < 4) {
        const float* A = g_xt + ((size_t)b * N_ + n0) * C_;
        const float* W; const float* bias; float* Out; int o0; bool rnd;
        if (yt < 2) { W = g_Wp + (size_t)(yt * 128) * C_;             bias = bf + yt * 128;       Out = g_ft + (size_t)b * N_ * HC_; o0 = yt * 128;       rnd = false; }
        else        { W = g_Wp + (size_t)(HC_ + (yt - 2) * 128) * C_; bias = bg + (yt - 2) * 128; Out = g_gt + (size_t)b * N_ * HC_; o0 = (yt - 2) * 128; rnd = true;  }
        gemm_core<3>(A, C_, W, C_, C_ / 32, acc);
        epi_store_perm(acc, Out + (size_t)n0 * HC_ + o0, HC_, bias, nullptr, rnd);
    } else {
        const int c0 = (yt - 4) * 128;
        const float* A  = g_Wp + (size_t)(2 * HC_ + c0) * C_;
        const float* Bm = g_xt + ((size_t)b * N_ + n0) * C_;
        gemm_core<3>(A, C_, Bm, C_, C_ / 32, acc);
        epi_store_perm(acc, g_h + (size_t)b * C_ * N_ + (size_t)c0 * N_ + n0, N_, nullptr, bh + c0, true);
    }
}

// energy: D[j][k] = ft[j][:] . gt[k][:] -> [j][k-perm]; narrow core, 2-pass.
__global__ __launch_bounds__(256, 2) void energy_kernel()
{
    const int b = blockIdx.z, k0 = blockIdx.x * 128, j0 = blockIdx.y * 128;
    const float* A  = g_ft + ((size_t)b * N_ + j0) * HC_;
    const float* Bm = g_gt + ((size_t)b * N_ + k0) * HC_;

    float acc[4][4][4] = {};
    gemm_core<2>(A, HC_, Bm, HC_, HC_ / 32, acc);
    epi_store_perm(acc, g_E + (size_t)b * N_ * N_ + (size_t)j0 * N_ + k0, N_, nullptr, nullptr, false);
}

// residual: D[c][j] = h[c][:] . corr[j][:] — wide tile 128x256, 1-pass.
__global__ __launch_bounds__(256, 1) void residual_kernel(float* __restrict__ out)
{
    const int b = blockIdx.z, c0 = blockIdx.x * 128, j0 = blockIdx.y * 256;
    const float* A  = g_h + (size_t)b * C_ * N_ + (size_t)c0 * N_;
    const float* Bm = g_E + (size_t)b * N_ * N_ + (size_t)j0 * N_;

    float acc[4][8][4] = {};
    gemm_core_w<1>(A, N_, Bm, N_, N_ / 32, acc);
    epi_store_w(acc, out + (size_t)b * C_ * N_ + (size_t)c0 * N_ + j0, N_);
}

// ---------------------------------------------------------------------------
// Softmax over 8 rows per block, float4-vectorized; writes corr rounded to
// tf32 AND per-block column partial sums (colmean fused).
// Thread owns columns tid*4 + i*1024 + {0..3}, i in 0..3.
// ---------------------------------------------------------------------------
__global__ __launch_bounds__(256) void softmax_kernel()
{
    const int b = blockIdx.y;
    const int j0 = blockIdx.x * 8;
    const int tid = threadIdx.x;
    __shared__ float red[8];

    float4 colacc[4];
    #pragma unroll
    for (int i = 0; i < 4; ++i) colacc[i] = make_float4(0.f, 0.f, 0.f, 0.f);

    for (int r = 0; r < 8; ++r) {
        float* row = g_E + ((size_t)b * N_ + j0 + r) * N_;

        float4 v[4];
        float m = -CUDART_INF_F;
        #pragma unroll
        for (int i = 0; i < 4; ++i) {
            v[i] = *reinterpret_cast<const float4*>(&row[tid * 4 + i * 1024]);
            m = fmaxf(m, fmaxf(fmaxf(v[i].x, v[i].y), fmaxf(v[i].z, v[i].w)));
        }

        #pragma unroll
        for (int o = 16; o; o >>= 1) m = fmaxf(m, __shfl_xor_sync(0xffffffffu, m, o));
        if ((tid & 31) == 0) red[tid >> 5] = m;
        __syncthreads();
        {
            float t = (tid < 8) ? red[tid] : -CUDART_INF_F;
            #pragma unroll
            for (int o = 4; o; o >>= 1) t = fmaxf(t, __shfl_xor_sync(0xffffffffu, t, o));
            if (tid == 0) red[0] = t;
        }
        __syncthreads();
        m = red[0];
        __syncthreads();

        float s = 0.f;
        #pragma unroll
        for (int i = 0; i < 4; ++i) {
            v[i].x = fast_exp_neg(v[i].x - m);
            v[i].y = fast_exp_neg(v[i].y - m);
            v[i].z = fast_exp_neg(v[i].z - m);
            v[i].w = fast_exp_neg(v[i].w - m);
            s += (v[i].x + v[i].y) + (v[i].z + v[i].w);
        }
        #pragma unroll
        for (int o = 16; o; o >>= 1) s += __shfl_xor_sync(0xffffffffu, s, o);
        if ((tid & 31) == 0) red[tid >> 5] = s;
        __syncthreads();
        {
            float t = (tid < 8) ? red[tid] : 0.f;
            #pragma unroll
            for (int o = 4; o; o >>= 1) t += __shfl_xor_sync(0xffffffffu, t, o);
            if (tid == 0) red[0] = t;
        }
        __syncthreads();
        const float inv = 1.0f / red[0];
        __syncthreads();

        #pragma unroll
        for (int i = 0; i < 4; ++i) {
            float4 c;
            c.x = __uint_as_float(f2tf(v[i].x * inv));
            c.y = __uint_as_float(f2tf(v[i].y * inv));
            c.z = __uint_as_float(f2tf(v[i].z * inv));
            c.w = __uint_as_float(f2tf(v[i].w * inv));
            *reinterpret_cast<float4*>(&row[tid * 4 + i * 1024]) = c;
            colacc[i].x += c.x; colacc[i].y += c.y;
            colacc[i].z += c.z; colacc[i].w += c.w;
        }
    }

    float* part = g_part + ((size_t)b * 512 + blockIdx.x) * N_;
    #pragma unroll
    for (int i = 0; i < 4; ++i)
        *reinterpret_cast<float4*>(&part[tid * 4 + i * 1024]) = colacc[i];
}

// Column mean final: sum 512 partials per column; un-permute output index.
__global__ __launch_bounds__(256) void colmean_final_kernel(float* __restrict__ out)
{
    const int b = blockIdx.y;
    const int col = blockIdx.x * 256 + threadIdx.x;  // permuted position
    const float* part = g_part + (size_t)b * 512 * N_;
    float s = 0.f;
    #pragma unroll 8
    for (int p = 0; p < 512; ++p) s += part[(size_t)p * N_ + col];
    const int m = (col & ~7) | ((col & 7) >> 1) | ((col & 1) << 2);  // iperm8
    out[(size_t)B_ * C_ * N_ + (size_t)b * N_ + m] = s * (1.0f / N_);
}

// ---------------------------------------------------------------------------
extern "C" void kernel_launch(void* const* d_in, const int* in_sizes, int n_in,
                              void* d_out, int out_size)
{
    const float* x  = (const float*)d_in[0];
    const float* Wf = (const float*)d_in[1];
    const float* bf = (const float*)d_in[2];
    const float* Wg = (const float*)d_in[3];
    const float* bg = (const float*)d_in[4];
    const float* Wh = (const float*)d_in[5];
    const float* bh = (const float*)d_in[6];
    float* out = (float*)d_out;

    const int SMEM = 98304;  // narrow: 3x32KB; wide: 2x48KB
    cudaFuncSetAttribute(proj_kernel,     cudaFuncAttributeMaxDynamicSharedMemorySize, SMEM);
    cudaFuncSetAttribute(energy_kernel,   cudaFuncAttributeMaxDynamicSharedMemorySize, SMEM);
    cudaFuncSetAttribute(residual_kernel, cudaFuncAttributeMaxDynamicSharedMemorySize, SMEM);

    const int NW = (HC_ + HC_ + C_) * C_;
    permute_w_kernel<<<(NW + 255) / 256, 256>>>(Wf, Wg, Wh);
    transpose_x_kernel<<<dim3(N_ / 32, C_ / 32, B_), dim3(32, 8)>>>(x);
    proj_kernel<<<dim3(32, 8, B_), 256, SMEM>>>(bf, bg, bh);
    energy_kernel<<<dim3(32, 32, B_), 256, SMEM>>>();
    softmax_kernel<<<dim3(512, B_), 256>>>();
    colmean_final_kernel<<<dim3(16, B_), 256>>>(out);
    residual_kernel<<<dim3(4, 16, B_), 256, SMEM>>>(out);
}